// round 1
// baseline (speedup 1.0000x reference)
#include <cuda_runtime.h>
#include <cuda_bf16.h>

#define N_NODES 50000
#define N_EDGES 800000
#define F_IN    512
#define F_HID   256
#define F_OUT   128

// Scratch (no allocations allowed): H0 = X@W1, H1 = spmm(H0), H2 = relu(H1)@W2
__device__ float g_H0[(size_t)N_NODES * F_HID];
__device__ float g_H1[(size_t)N_NODES * F_HID];
__device__ float g_H2[(size_t)N_NODES * F_OUT];

// ---------------------------------------------------------------------------
// Zero kernel (float4)
// ---------------------------------------------------------------------------
__global__ void zero_kernel(float4* __restrict__ p, int n4) {
    int i = blockIdx.x * blockDim.x + threadIdx.x;
    if (i < n4) p[i] = make_float4(0.f, 0.f, 0.f, 0.f);
}

// ---------------------------------------------------------------------------
// Tiled fp32 GEMM: C[M,N] = op(A)[M,K] @ B[K,N]
// BM=BN=64, BK=16, 256 threads, 4x4 per thread. RELU_A applies relu to A loads.
// Assumes N % BN == 0 and K % BK == 0 (true here); M is bounds-checked.
// ---------------------------------------------------------------------------
template<bool RELU_A>
__global__ __launch_bounds__(256)
void gemm_kernel(const float* __restrict__ A, const float* __restrict__ B,
                 float* __restrict__ C, int M, int N, int K) {
    constexpr int BM = 64, BN = 64, BK = 16, TM = 4, TN = 4;
    __shared__ float As[BK][BM];
    __shared__ float Bs[BK][BN];

    const int tx = threadIdx.x % (BN / TN);   // 0..15
    const int ty = threadIdx.x / (BN / TN);   // 0..15
    const int row0 = blockIdx.y * BM;
    const int col0 = blockIdx.x * BN;

    float acc[TM][TN] = {};

    for (int k0 = 0; k0 < K; k0 += BK) {
        // Load A tile (BM x BK) -> As[k][m]
        #pragma unroll
        for (int i = threadIdx.x; i < BM * BK; i += 256) {
            int m = i / BK, k = i % BK;
            int gr = row0 + m;
            float v = (gr < M) ? A[(size_t)gr * K + k0 + k] : 0.f;
            if (RELU_A) v = fmaxf(v, 0.f);
            As[k][m] = v;
        }
        // Load B tile (BK x BN) -> Bs[k][n]
        #pragma unroll
        for (int i = threadIdx.x; i < BK * BN; i += 256) {
            int k = i / BN, n = i % BN;
            Bs[k][n] = B[(size_t)(k0 + k) * N + col0 + n];
        }
        __syncthreads();

        #pragma unroll
        for (int k = 0; k < BK; k++) {
            float a[TM], b[TN];
            #pragma unroll
            for (int i = 0; i < TM; i++) a[i] = As[k][ty * TM + i];
            #pragma unroll
            for (int j = 0; j < TN; j++) b[j] = Bs[k][tx * TN + j];
            #pragma unroll
            for (int i = 0; i < TM; i++)
                #pragma unroll
                for (int j = 0; j < TN; j++)
                    acc[i][j] = fmaf(a[i], b[j], acc[i][j]);
        }
        __syncthreads();
    }

    #pragma unroll
    for (int i = 0; i < TM; i++) {
        int r = row0 + ty * TM + i;
        if (r < M) {
            #pragma unroll
            for (int j = 0; j < TN; j++)
                C[(size_t)r * N + col0 + tx * TN + j] = acc[i][j];
        }
    }
}

// ---------------------------------------------------------------------------
// Edge-parallel SpMM: y[dst[e]] += w[e] * x[src[e]]  (atomic scatter)
// One thread per (edge, 4-feature group). F must be a multiple of 4.
// ---------------------------------------------------------------------------
template<int F>
__global__ __launch_bounds__(256)
void spmm_kernel(const int* __restrict__ src, const int* __restrict__ dst,
                 const float* __restrict__ w, const float* __restrict__ x,
                 float* __restrict__ y) {
    constexpr int F4 = F / 4;
    long long tid = (long long)blockIdx.x * blockDim.x + threadIdx.x;
    if (tid >= (long long)N_EDGES * F4) return;
    int e = (int)(tid >> (F4 == 64 ? 6 : 5));      // tid / F4 (F4 is 64 or 32)
    int f = ((int)tid & (F4 - 1)) * 4;

    float wv = __ldg(&w[e]);
    int s = __ldg(&src[e]);
    int d = __ldg(&dst[e]);

    float4 v = *(const float4*)(x + (size_t)s * F + f);
    float* yp = y + (size_t)d * F + f;
    atomicAdd(yp + 0, wv * v.x);
    atomicAdd(yp + 1, wv * v.y);
    atomicAdd(yp + 2, wv * v.z);
    atomicAdd(yp + 3, wv * v.w);
}

// ---------------------------------------------------------------------------
// Launch
// ---------------------------------------------------------------------------
extern "C" void kernel_launch(void* const* d_in, const int* in_sizes, int n_in,
                              void* d_out, int out_size) {
    const float* X    = (const float*)d_in[0];   // [N_NODES, F_IN]
    const int*   esrc = (const int*)  d_in[1];   // [N_EDGES]
    const int*   edst = (const int*)  d_in[2];   // [N_EDGES]
    const float* ew   = (const float*)d_in[3];   // [N_EDGES]
    const float* W1   = (const float*)d_in[4];   // [F_IN, F_HID]
    const float* W2   = (const float*)d_in[5];   // [F_HID, F_OUT]
    float* out = (float*)d_out;                  // [N_NODES, F_OUT]

    float *H0, *H1, *H2;
    cudaGetSymbolAddress((void**)&H0, g_H0);
    cudaGetSymbolAddress((void**)&H1, g_H1);
    cudaGetSymbolAddress((void**)&H2, g_H2);

    const int THREADS = 256;

    // H0 = X @ W1
    {
        dim3 grid(F_HID / 64, (N_NODES + 63) / 64);
        gemm_kernel<false><<<grid, THREADS>>>(X, W1, H0, N_NODES, F_HID, F_IN);
    }
    // H1 = 0 ; H1 += scatter(w * H0[src])
    {
        int n4 = N_NODES * F_HID / 4;
        zero_kernel<<<(n4 + THREADS - 1) / THREADS, THREADS>>>((float4*)H1, n4);
        long long total = (long long)N_EDGES * (F_HID / 4);
        int blocks = (int)((total + THREADS - 1) / THREADS);
        spmm_kernel<F_HID><<<blocks, THREADS>>>(esrc, edst, ew, H0, H1);
    }
    // H2 = relu(H1) @ W2
    {
        dim3 grid(F_OUT / 64, (N_NODES + 63) / 64);
        gemm_kernel<true><<<grid, THREADS>>>(H1, W2, H2, N_NODES, F_OUT, F_HID);
    }
    // out = 0 ; out += scatter(w * H2[src])
    {
        int n4 = N_NODES * F_OUT / 4;
        zero_kernel<<<(n4 + THREADS - 1) / THREADS, THREADS>>>((float4*)out, n4);
        long long total = (long long)N_EDGES * (F_OUT / 4);
        int blocks = (int)((total + THREADS - 1) / THREADS);
        spmm_kernel<F_OUT><<<blocks, THREADS>>>(esrc, edst, ew, H2, out);
    }
}

// round 2
// speedup vs baseline: 1.9220x; 1.9220x over previous
#include <cuda_runtime.h>
#include <cuda_bf16.h>

#define N_NODES 50000
#define N_EDGES 800000
#define F_IN    512
#define F_HID   256
#define F_OUT   128

// Scratch: H0 = X@W1, H1 = spmm(H0), H2 = relu(H1)@W2
__device__ float g_H0[(size_t)N_NODES * F_HID];
__device__ float g_H1[(size_t)N_NODES * F_HID];
__device__ float g_H2[(size_t)N_NODES * F_OUT];

// ---------------------------------------------------------------------------
// Zero kernel (float4)
// ---------------------------------------------------------------------------
__global__ void zero_kernel(float4* __restrict__ p, int n4) {
    int i = blockIdx.x * blockDim.x + threadIdx.x;
    if (i < n4) p[i] = make_float4(0.f, 0.f, 0.f, 0.f);
}

// ---------------------------------------------------------------------------
// Tiled fp32 GEMM: C[M,N] = op(A)[M,K] @ B[K,N]
// BM=128, BN=64, BK=16, 256 threads, 8x4 per thread, float4 global loads.
// Requires N % 64 == 0, K % 16 == 0 (true here). M bounds-checked.
// ---------------------------------------------------------------------------
template<bool RELU_A>
__global__ __launch_bounds__(256)
void gemm_kernel(const float* __restrict__ A, const float* __restrict__ B,
                 float* __restrict__ C, int M, int N, int K) {
    constexpr int BM = 128, BN = 64, BK = 16, TM = 8, TN = 4;
    __shared__ float As[BK][BM];   // transposed A tile
    __shared__ float Bs[BK][BN];

    const int tid = threadIdx.x;
    const int tx = tid % (BN / TN);   // 0..15 (N dir)
    const int ty = tid / (BN / TN);   // 0..15 (M dir)
    const int row0 = blockIdx.y * BM;
    const int col0 = blockIdx.x * BN;

    // A-load mapping: thread -> (row = tid/4 [+64], colgroup = tid%4)
    const int a_row = tid / 4;        // 0..63
    const int a_cg  = (tid % 4) * 4;  // 0,4,8,12
    // B-load mapping: thread -> (k = tid/16, colgroup = tid%16)
    const int b_k   = tid / 16;       // 0..15
    const int b_cg  = (tid % 16) * 4;

    float acc[TM][TN] = {};

    for (int k0 = 0; k0 < K; k0 += BK) {
        // ---- load A tile (BM x BK), two float4 per thread, store transposed
        #pragma unroll
        for (int half = 0; half < 2; half++) {
            int m = a_row + half * 64;
            int gr = row0 + m;
            float4 v;
            if (gr < M) {
                v = *(const float4*)(A + (size_t)gr * K + k0 + a_cg);
                if (RELU_A) {
                    v.x = fmaxf(v.x, 0.f); v.y = fmaxf(v.y, 0.f);
                    v.z = fmaxf(v.z, 0.f); v.w = fmaxf(v.w, 0.f);
                }
            } else {
                v = make_float4(0.f, 0.f, 0.f, 0.f);
            }
            As[a_cg + 0][m] = v.x;
            As[a_cg + 1][m] = v.y;
            As[a_cg + 2][m] = v.z;
            As[a_cg + 3][m] = v.w;
        }
        // ---- load B tile (BK x BN), one float4 per thread
        {
            float4 v = *(const float4*)(B + (size_t)(k0 + b_k) * N + col0 + b_cg);
            *(float4*)(&Bs[b_k][b_cg]) = v;
        }
        __syncthreads();

        #pragma unroll
        for (int k = 0; k < BK; k++) {
            float a[TM], b[TN];
            float4 a0 = *(const float4*)(&As[k][ty * TM]);
            float4 a1 = *(const float4*)(&As[k][ty * TM + 4]);
            a[0]=a0.x; a[1]=a0.y; a[2]=a0.z; a[3]=a0.w;
            a[4]=a1.x; a[5]=a1.y; a[6]=a1.z; a[7]=a1.w;
            float4 bv = *(const float4*)(&Bs[k][tx * TN]);
            b[0]=bv.x; b[1]=bv.y; b[2]=bv.z; b[3]=bv.w;
            #pragma unroll
            for (int i = 0; i < TM; i++)
                #pragma unroll
                for (int j = 0; j < TN; j++)
                    acc[i][j] = fmaf(a[i], b[j], acc[i][j]);
        }
        __syncthreads();
    }

    #pragma unroll
    for (int i = 0; i < TM; i++) {
        int r = row0 + ty * TM + i;
        if (r < M) {
            float4 v = make_float4(acc[i][0], acc[i][1], acc[i][2], acc[i][3]);
            *(float4*)(C + (size_t)r * N + col0 + tx * TN) = v;
        }
    }
}

// ---------------------------------------------------------------------------
// Edge-parallel SpMM: y[dst[e]] += w[e] * x[src[e]]
// One thread per (edge, 4-feature group); red.global.add.v4.f32 scatter.
// ---------------------------------------------------------------------------
template<int F>
__global__ __launch_bounds__(256)
void spmm_kernel(const int* __restrict__ src, const int* __restrict__ dst,
                 const float* __restrict__ w, const float* __restrict__ x,
                 float* __restrict__ y) {
    constexpr int F4 = F / 4;
    long long tid = (long long)blockIdx.x * blockDim.x + threadIdx.x;
    if (tid >= (long long)N_EDGES * F4) return;
    int e = (int)(tid / F4);
    int f = ((int)tid % F4) * 4;

    float wv = __ldg(&w[e]);
    int s = __ldg(&src[e]);
    int d = __ldg(&dst[e]);

    float4 v = *(const float4*)(x + (size_t)s * F + f);
    float* yp = y + (size_t)d * F + f;
    asm volatile("red.global.add.v4.f32 [%0], {%1, %2, %3, %4};"
                 :: "l"(yp), "f"(wv * v.x), "f"(wv * v.y),
                    "f"(wv * v.z), "f"(wv * v.w)
                 : "memory");
}

// ---------------------------------------------------------------------------
// Launch
// ---------------------------------------------------------------------------
extern "C" void kernel_launch(void* const* d_in, const int* in_sizes, int n_in,
                              void* d_out, int out_size) {
    const float* X    = (const float*)d_in[0];   // [N_NODES, F_IN]
    const int*   esrc = (const int*)  d_in[1];   // [N_EDGES]
    const int*   edst = (const int*)  d_in[2];   // [N_EDGES]
    const float* ew   = (const float*)d_in[3];   // [N_EDGES]
    const float* W1   = (const float*)d_in[4];   // [F_IN, F_HID]
    const float* W2   = (const float*)d_in[5];   // [F_HID, F_OUT]
    float* out = (float*)d_out;                  // [N_NODES, F_OUT]

    float *H0, *H1, *H2;
    cudaGetSymbolAddress((void**)&H0, g_H0);
    cudaGetSymbolAddress((void**)&H1, g_H1);
    cudaGetSymbolAddress((void**)&H2, g_H2);

    const int THREADS = 256;

    // H0 = X @ W1
    {
        dim3 grid(F_HID / 64, (N_NODES + 127) / 128);
        gemm_kernel<false><<<grid, THREADS>>>(X, W1, H0, N_NODES, F_HID, F_IN);
    }
    // H1 = 0 ; H1 += scatter(w * H0[src])
    {
        int n4 = N_NODES * F_HID / 4;
        zero_kernel<<<(n4 + THREADS - 1) / THREADS, THREADS>>>((float4*)H1, n4);
        long long total = (long long)N_EDGES * (F_HID / 4);
        int blocks = (int)((total + THREADS - 1) / THREADS);
        spmm_kernel<F_HID><<<blocks, THREADS>>>(esrc, edst, ew, H0, H1);
    }
    // H2 = relu(H1) @ W2
    {
        dim3 grid(F_OUT / 64, (N_NODES + 127) / 128);
        gemm_kernel<true><<<grid, THREADS>>>(H1, W2, H2, N_NODES, F_OUT, F_HID);
    }
    // out = 0 ; out += scatter(w * H2[src])
    {
        int n4 = N_NODES * F_OUT / 4;
        zero_kernel<<<(n4 + THREADS - 1) / THREADS, THREADS>>>((float4*)out, n4);
        long long total = (long long)N_EDGES * (F_OUT / 4);
        int blocks = (int)((total + THREADS - 1) / THREADS);
        spmm_kernel<F_OUT><<<blocks, THREADS>>>(esrc, edst, ew, H2, out);
    }
}

// round 3
// speedup vs baseline: 2.3526x; 1.2241x over previous
#include <cuda_runtime.h>
#include <cuda_bf16.h>

#define N_NODES 50000
#define N_EDGES 800000
#define F_IN    512
#define F_HID   256
#define F_OUT   128

// Scratch: H0 = X@W1, H1 = spmm(H0), H2 = relu(H1)@W2
__device__ float g_H0[(size_t)N_NODES * F_HID];
__device__ float g_H1[(size_t)N_NODES * F_HID];
__device__ float g_H2[(size_t)N_NODES * F_OUT];

// ---------------------------------------------------------------------------
// Zero kernel (float4)
// ---------------------------------------------------------------------------
__global__ void zero_kernel(float4* __restrict__ p, int n4) {
    int i = blockIdx.x * blockDim.x + threadIdx.x;
    if (i < n4) p[i] = make_float4(0.f, 0.f, 0.f, 0.f);
}

// ---------------------------------------------------------------------------
// tf32 helpers
// ---------------------------------------------------------------------------
__device__ __forceinline__ unsigned f2tf32(float x) {
    unsigned r;
    asm("cvt.rna.tf32.f32 %0, %1;" : "=r"(r) : "f"(x));
    return r;
}

__device__ __forceinline__ void mma_tf32(float c[4], const unsigned a[4],
                                         const unsigned b[2]) {
    asm volatile(
        "mma.sync.aligned.m16n8k8.row.col.f32.tf32.tf32.f32 "
        "{%0,%1,%2,%3}, {%4,%5,%6,%7}, {%8,%9}, {%0,%1,%2,%3};"
        : "+f"(c[0]), "+f"(c[1]), "+f"(c[2]), "+f"(c[3])
        : "r"(a[0]), "r"(a[1]), "r"(a[2]), "r"(a[3]), "r"(b[0]), "r"(b[1]));
}

// ---------------------------------------------------------------------------
// 3xTF32 tensor-core GEMM: C[M,N] = op(A)[M,K] @ B[K,N]
// Block 128x64, 8 warps (4x2), warp tile 32x32 (2 mtiles x 4 ntiles of
// m16n8k8). BK=32. Full fp32-class accuracy via hi/lo tf32 split (3 MMAs).
// Requires N % 64 == 0, K % 32 == 0. M bounds-checked.
// ---------------------------------------------------------------------------
template<bool RELU_A>
__global__ __launch_bounds__(256)
void gemm_tc_kernel(const float* __restrict__ A, const float* __restrict__ B,
                    float* __restrict__ C, int M, int N, int K) {
    constexpr int BM = 128, BN = 64, BK = 32;
    __shared__ float As[BM][BK + 4];   // [m][k], pitch 36 -> conflict-free frags
    __shared__ float Bs[BK][BN + 4];   // [k][n], pitch 68

    const int tid = threadIdx.x;
    const int lane = tid & 31;
    const int warp = tid >> 5;
    const int g   = lane >> 2;     // groupID 0..7
    const int tig = lane & 3;      // thread-in-group 0..3
    const int warp_m = warp & 3;   // 0..3
    const int warp_n = warp >> 2;  // 0..1

    const int row0 = blockIdx.y * BM;
    const int col0 = blockIdx.x * BN;

    // A global-load map: 4 passes of (row = tid/8 + 32*p, kg = (tid%8)*4)
    const int a_r  = tid >> 3;          // 0..31
    const int a_kg = (tid & 7) * 4;     // 0,4,...,28
    // B global-load map: 2 passes of (k = tid/16 + 16*p, cg = (tid%16)*4)
    const int b_k  = tid >> 4;          // 0..15
    const int b_cg = (tid & 15) * 4;

    float acc[2][4][4];
    #pragma unroll
    for (int i = 0; i < 2; i++)
        #pragma unroll
        for (int j = 0; j < 4; j++)
            #pragma unroll
            for (int l = 0; l < 4; l++) acc[i][j][l] = 0.f;

    for (int k0 = 0; k0 < K; k0 += BK) {
        // ---- A tile (BM x BK) -> As[m][k]
        #pragma unroll
        for (int p = 0; p < 4; p++) {
            int m = a_r + 32 * p;
            int gr = row0 + m;
            float4 v;
            if (gr < M) {
                v = *(const float4*)(A + (size_t)gr * K + k0 + a_kg);
                if (RELU_A) {
                    v.x = fmaxf(v.x, 0.f); v.y = fmaxf(v.y, 0.f);
                    v.z = fmaxf(v.z, 0.f); v.w = fmaxf(v.w, 0.f);
                }
            } else {
                v = make_float4(0.f, 0.f, 0.f, 0.f);
            }
            *(float4*)(&As[m][a_kg]) = v;
        }
        // ---- B tile (BK x BN) -> Bs[k][n]
        #pragma unroll
        for (int p = 0; p < 2; p++) {
            int k = b_k + 16 * p;
            float4 v = *(const float4*)(B + (size_t)(k0 + k) * N + col0 + b_cg);
            *(float4*)(&Bs[k][b_cg]) = v;
        }
        __syncthreads();

        #pragma unroll
        for (int kk = 0; kk < BK; kk += 8) {
            // load + split A fragments (2 mtiles)
            unsigned a_hi[2][4], a_lo[2][4];
            #pragma unroll
            for (int mt = 0; mt < 2; mt++) {
                int rb = warp_m * 32 + mt * 16 + g;
                float f[4];
                f[0] = As[rb    ][kk + tig];
                f[1] = As[rb + 8][kk + tig];
                f[2] = As[rb    ][kk + tig + 4];
                f[3] = As[rb + 8][kk + tig + 4];
                #pragma unroll
                for (int q = 0; q < 4; q++) {
                    a_hi[mt][q] = f2tf32(f[q]);
                    a_lo[mt][q] = f2tf32(f[q] - __uint_as_float(a_hi[mt][q]));
                }
            }
            // load + split B fragments (4 ntiles)
            unsigned b_hi[4][2], b_lo[4][2];
            #pragma unroll
            for (int nt = 0; nt < 4; nt++) {
                int cb = warp_n * 32 + nt * 8 + g;
                float f[2];
                f[0] = Bs[kk + tig    ][cb];
                f[1] = Bs[kk + tig + 4][cb];
                #pragma unroll
                for (int q = 0; q < 2; q++) {
                    b_hi[nt][q] = f2tf32(f[q]);
                    b_lo[nt][q] = f2tf32(f[q] - __uint_as_float(b_hi[nt][q]));
                }
            }
            // 3xTF32 MMAs
            #pragma unroll
            for (int mt = 0; mt < 2; mt++)
                #pragma unroll
                for (int nt = 0; nt < 4; nt++) {
                    mma_tf32(acc[mt][nt], a_lo[mt], b_hi[nt]);
                    mma_tf32(acc[mt][nt], a_hi[mt], b_lo[nt]);
                    mma_tf32(acc[mt][nt], a_hi[mt], b_hi[nt]);
                }
        }
        __syncthreads();
    }

    // ---- store C
    #pragma unroll
    for (int mt = 0; mt < 2; mt++) {
        int r_lo = row0 + warp_m * 32 + mt * 16 + g;
        int r_hi = r_lo + 8;
        #pragma unroll
        for (int nt = 0; nt < 4; nt++) {
            int c = col0 + warp_n * 32 + nt * 8 + 2 * tig;
            if (r_lo < M)
                *(float2*)(C + (size_t)r_lo * N + c) =
                    make_float2(acc[mt][nt][0], acc[mt][nt][1]);
            if (r_hi < M)
                *(float2*)(C + (size_t)r_hi * N + c) =
                    make_float2(acc[mt][nt][2], acc[mt][nt][3]);
        }
    }
}

// ---------------------------------------------------------------------------
// Warp-per-edge SpMM: y[dst[e]] += w[e] * x[src[e]]
// Indices loaded once per warp (broadcast); coalesced gather + RED.v4 scatter.
// ---------------------------------------------------------------------------
template<int F>
__global__ __launch_bounds__(256)
void spmm_kernel(const int* __restrict__ src, const int* __restrict__ dst,
                 const float* __restrict__ w, const float* __restrict__ x,
                 float* __restrict__ y) {
    constexpr int F4 = F / 4;
    int e = blockIdx.x * 8 + (threadIdx.x >> 5);
    if (e >= N_EDGES) return;
    int lane = threadIdx.x & 31;

    float wv = __ldg(&w[e]);
    int s = __ldg(&src[e]);
    int d = __ldg(&dst[e]);

    const float4* xr = (const float4*)(x + (size_t)s * F);
    float* yr = y + (size_t)d * F;

    #pragma unroll
    for (int c = lane; c < F4; c += 32) {
        float4 v = __ldg(&xr[c]);
        float* yp = yr + c * 4;
        asm volatile("red.global.add.v4.f32 [%0], {%1, %2, %3, %4};"
                     :: "l"(yp), "f"(wv * v.x), "f"(wv * v.y),
                        "f"(wv * v.z), "f"(wv * v.w)
                     : "memory");
    }
}

// ---------------------------------------------------------------------------
// Launch
// ---------------------------------------------------------------------------
extern "C" void kernel_launch(void* const* d_in, const int* in_sizes, int n_in,
                              void* d_out, int out_size) {
    const float* X    = (const float*)d_in[0];   // [N_NODES, F_IN]
    const int*   esrc = (const int*)  d_in[1];   // [N_EDGES]
    const int*   edst = (const int*)  d_in[2];   // [N_EDGES]
    const float* ew   = (const float*)d_in[3];   // [N_EDGES]
    const float* W1   = (const float*)d_in[4];   // [F_IN, F_HID]
    const float* W2   = (const float*)d_in[5];   // [F_HID, F_OUT]
    float* out = (float*)d_out;                  // [N_NODES, F_OUT]

    float *H0, *H1, *H2;
    cudaGetSymbolAddress((void**)&H0, g_H0);
    cudaGetSymbolAddress((void**)&H1, g_H1);
    cudaGetSymbolAddress((void**)&H2, g_H2);

    const int THREADS = 256;
    const int MB = (N_NODES + 127) / 128;
    const int spmm_blocks = (N_EDGES + 7) / 8;

    // H0 = X @ W1
    gemm_tc_kernel<false><<<dim3(F_HID / 64, MB), THREADS>>>(X, W1, H0,
                                                             N_NODES, F_HID, F_IN);
    // H1 = 0 ; H1 += scatter(w * H0[src])
    {
        int n4 = N_NODES * F_HID / 4;
        zero_kernel<<<(n4 + THREADS - 1) / THREADS, THREADS>>>((float4*)H1, n4);
        spmm_kernel<F_HID><<<spmm_blocks, THREADS>>>(esrc, edst, ew, H0, H1);
    }
    // H2 = relu(H1) @ W2
    gemm_tc_kernel<true><<<dim3(F_OUT / 64, MB), THREADS>>>(H1, W2, H2,
                                                            N_NODES, F_OUT, F_HID);
    // out = 0 ; out += scatter(w * H2[src])
    {
        int n4 = N_NODES * F_OUT / 4;
        zero_kernel<<<(n4 + THREADS - 1) / THREADS, THREADS>>>((float4*)out, n4);
        spmm_kernel<F_OUT><<<spmm_blocks, THREADS>>>(esrc, edst, ew, H2, out);
    }
}

// round 5
// speedup vs baseline: 2.4352x; 1.0351x over previous
#include <cuda_runtime.h>
#include <cuda_bf16.h>

#define N_NODES 50000
#define N_EDGES 800000
#define F_IN    512
#define F_HID   256
#define F_OUT   128

// Scratch: H0 = X@W1, H1 = spmm(H0), H2 = relu(H1)@W2
__device__ float g_H0[(size_t)N_NODES * F_HID];
__device__ float g_H1[(size_t)N_NODES * F_HID];
__device__ float g_H2[(size_t)N_NODES * F_OUT];

// ---------------------------------------------------------------------------
// Zero kernel (float4)
// ---------------------------------------------------------------------------
__global__ void zero_kernel(float4* __restrict__ p, int n4) {
    int i = blockIdx.x * blockDim.x + threadIdx.x;
    if (i < n4) p[i] = make_float4(0.f, 0.f, 0.f, 0.f);
}

// ---------------------------------------------------------------------------
// helpers
// ---------------------------------------------------------------------------
__device__ __forceinline__ unsigned f2tf32(float x) {
    unsigned r;
    asm("cvt.rna.tf32.f32 %0, %1;" : "=r"(r) : "f"(x));
    return r;
}

__device__ __forceinline__ void mma_tf32(float c[4], const unsigned a[4],
                                         const unsigned b[2]) {
    asm volatile(
        "mma.sync.aligned.m16n8k8.row.col.f32.tf32.tf32.f32 "
        "{%0,%1,%2,%3}, {%4,%5,%6,%7}, {%8,%9}, {%0,%1,%2,%3};"
        : "+f"(c[0]), "+f"(c[1]), "+f"(c[2]), "+f"(c[3])
        : "r"(a[0]), "r"(a[1]), "r"(a[2]), "r"(a[3]), "r"(b[0]), "r"(b[1]));
}

__device__ __forceinline__ unsigned smem_u32(const void* p) {
    return (unsigned)__cvta_generic_to_shared(p);
}

__device__ __forceinline__ void cp_async16(unsigned dst, const void* src, int src_bytes) {
    asm volatile("cp.async.ca.shared.global [%0], [%1], 16, %2;"
                 :: "r"(dst), "l"(src), "r"(src_bytes));
}
#define CP_COMMIT() asm volatile("cp.async.commit_group;")
#define CP_WAIT_1() asm volatile("cp.async.wait_group 1;")
#define CP_WAIT_0() asm volatile("cp.async.wait_group 0;")

// ---------------------------------------------------------------------------
// 3xTF32 tensor-core GEMM, cp.async double-buffered.
// C[M,N] = op(A)[M,K] @ B[K,N]. Block 128x128, BK=16, 8 warps (2x4),
// warp tile 64x32 (4 mtiles x 4 ntiles of m16n8k8).
// Requires N % 128 == 0, K % 16 == 0. M bounds-checked.
// ---------------------------------------------------------------------------
template<bool RELU_A>
__global__ __launch_bounds__(256)
void gemm_tc_kernel(const float* __restrict__ A, const float* __restrict__ B,
                    float* __restrict__ C, int M, int N, int K) {
    constexpr int BM = 128, BN = 128, BK = 16;
    __shared__ __align__(16) float As[2][BM][BK + 4];   // [m][k], pitch 20
    __shared__ __align__(16) float Bs[2][BK][BN + 4];   // [k][n], pitch 132

    const int tid  = threadIdx.x;
    const int lane = tid & 31;
    const int warp = tid >> 5;
    const int g    = lane >> 2;     // groupID 0..7
    const int tig  = lane & 3;      // thread-in-group 0..3
    const int warp_m = warp & 1;    // 0..1 (64 rows each)
    const int warp_n = warp >> 1;   // 0..3 (32 cols each)

    const int row0 = blockIdx.y * BM;
    const int col0 = blockIdx.x * BN;

    float acc[4][4][4];
    #pragma unroll
    for (int i = 0; i < 4; i++)
        #pragma unroll
        for (int j = 0; j < 4; j++)
            #pragma unroll
            for (int l = 0; l < 4; l++) acc[i][j][l] = 0.f;

    auto load_tile = [&](int s, int k0) {
        // A: 128 rows x 16 cols = 512 float4; row = idx/4, kq = idx%4
        #pragma unroll
        for (int p = 0; p < 2; p++) {
            int idx = tid + p * 256;
            int m = idx >> 2, kq = idx & 3;
            int gr = row0 + m;
            const float* src = A + (size_t)(gr < M ? gr : 0) * K + k0 + kq * 4;
            cp_async16(smem_u32(&As[s][m][kq * 4]), src, gr < M ? 16 : 0);
        }
        // B: 16 rows x 128 cols = 512 float4; k = idx/32, cq = idx%32
        #pragma unroll
        for (int p = 0; p < 2; p++) {
            int idx = tid + p * 256;
            int kr = idx >> 5, cq = idx & 31;
            const float* src = B + (size_t)(k0 + kr) * N + col0 + cq * 4;
            cp_async16(smem_u32(&Bs[s][kr][cq * 4]), src, 16);
        }
    };

    auto compute = [&](int s) {
        #pragma unroll
        for (int kk = 0; kk < BK; kk += 8) {
            unsigned a_hi[4][4], a_lo[4][4];
            #pragma unroll
            for (int mt = 0; mt < 4; mt++) {
                int rb = warp_m * 64 + mt * 16 + g;
                float f[4];
                f[0] = As[s][rb    ][kk + tig];
                f[1] = As[s][rb + 8][kk + tig];
                f[2] = As[s][rb    ][kk + tig + 4];
                f[3] = As[s][rb + 8][kk + tig + 4];
                #pragma unroll
                for (int q = 0; q < 4; q++) {
                    if (RELU_A) f[q] = fmaxf(f[q], 0.f);
                    a_hi[mt][q] = f2tf32(f[q]);
                    a_lo[mt][q] = f2tf32(f[q] - __uint_as_float(a_hi[mt][q]));
                }
            }
            unsigned b_hi[4][2], b_lo[4][2];
            #pragma unroll
            for (int nt = 0; nt < 4; nt++) {
                int cb = warp_n * 32 + nt * 8 + g;
                float f[2];
                f[0] = Bs[s][kk + tig    ][cb];
                f[1] = Bs[s][kk + tig + 4][cb];
                #pragma unroll
                for (int q = 0; q < 2; q++) {
                    b_hi[nt][q] = f2tf32(f[q]);
                    b_lo[nt][q] = f2tf32(f[q] - __uint_as_float(b_hi[nt][q]));
                }
            }
            #pragma unroll
            for (int mt = 0; mt < 4; mt++)
                #pragma unroll
                for (int nt = 0; nt < 4; nt++) {
                    mma_tf32(acc[mt][nt], a_lo[mt], b_hi[nt]);
                    mma_tf32(acc[mt][nt], a_hi[mt], b_lo[nt]);
                    mma_tf32(acc[mt][nt], a_hi[mt], b_hi[nt]);
                }
        }
    };

    const int T = K / BK;
    load_tile(0, 0);
    CP_COMMIT();
    for (int t = 0; t < T; t++) {
        if (t + 1 < T) {
            load_tile((t + 1) & 1, (t + 1) * BK);
            CP_COMMIT();
            CP_WAIT_1();
        } else {
            CP_WAIT_0();
        }
        __syncthreads();
        compute(t & 1);
        __syncthreads();
    }

    // ---- store C
    #pragma unroll
    for (int mt = 0; mt < 4; mt++) {
        int r_lo = row0 + warp_m * 64 + mt * 16 + g;
        int r_hi = r_lo + 8;
        #pragma unroll
        for (int nt = 0; nt < 4; nt++) {
            int c = col0 + warp_n * 32 + nt * 8 + 2 * tig;
            if (r_lo < M)
                *(float2*)(C + (size_t)r_lo * N + c) =
                    make_float2(acc[mt][nt][0], acc[mt][nt][1]);
            if (r_hi < M)
                *(float2*)(C + (size_t)r_hi * N + c) =
                    make_float2(acc[mt][nt][2], acc[mt][nt][3]);
        }
    }
}

// ---------------------------------------------------------------------------
// Warp-per-edge SpMM: y[dst[e]] += w[e] * x[src[e]]
// ---------------------------------------------------------------------------
template<int F>
__global__ __launch_bounds__(256)
void spmm_kernel(const int* __restrict__ src, const int* __restrict__ dst,
                 const float* __restrict__ w, const float* __restrict__ x,
                 float* __restrict__ y) {
    constexpr int F4 = F / 4;
    int e = blockIdx.x * 8 + (threadIdx.x >> 5);
    if (e >= N_EDGES) return;
    int lane = threadIdx.x & 31;

    float wv = __ldg(&w[e]);
    int s = __ldg(&src[e]);
    int d = __ldg(&dst[e]);

    const float4* xr = (const float4*)(x + (size_t)s * F);
    float* yr = y + (size_t)d * F;

    #pragma unroll
    for (int c = lane; c < F4; c += 32) {
        float4 v = __ldg(&xr[c]);
        float* yp = yr + c * 4;
        asm volatile("red.global.add.v4.f32 [%0], {%1, %2, %3, %4};"
                     :: "l"(yp), "f"(wv * v.x), "f"(wv * v.y),
                        "f"(wv * v.z), "f"(wv * v.w)
                     : "memory");
    }
}

// ---------------------------------------------------------------------------
// Launch
// ---------------------------------------------------------------------------
extern "C" void kernel_launch(void* const* d_in, const int* in_sizes, int n_in,
                              void* d_out, int out_size) {
    const float* X    = (const float*)d_in[0];   // [N_NODES, F_IN]
    const int*   esrc = (const int*)  d_in[1];   // [N_EDGES]
    const int*   edst = (const int*)  d_in[2];   // [N_EDGES]
    const float* ew   = (const float*)d_in[3];   // [N_EDGES]
    const float* W1   = (const float*)d_in[4];   // [F_IN, F_HID]
    const float* W2   = (const float*)d_in[5];   // [F_HID, F_OUT]
    float* out = (float*)d_out;                  // [N_NODES, F_OUT]

    float *H0, *H1, *H2;
    cudaGetSymbolAddress((void**)&H0, g_H0);
    cudaGetSymbolAddress((void**)&H1, g_H1);
    cudaGetSymbolAddress((void**)&H2, g_H2);

    const int THREADS = 256;
    const int MB = (N_NODES + 127) / 128;
    const int spmm_blocks = (N_EDGES + 7) / 8;

    // H0 = X @ W1
    gemm_tc_kernel<false><<<dim3(F_HID / 128, MB), THREADS>>>(X, W1, H0,
                                                              N_NODES, F_HID, F_IN);
    // H1 = 0 ; H1 += scatter(w * H0[src])
    {
        int n4 = N_NODES * F_HID / 4;
        zero_kernel<<<(n4 + THREADS - 1) / THREADS, THREADS>>>((float4*)H1, n4);
        spmm_kernel<F_HID><<<spmm_blocks, THREADS>>>(esrc, edst, ew, H0, H1);
    }
    // H2 = relu(H1) @ W2
    gemm_tc_kernel<true><<<dim3(F_OUT / 128, MB), THREADS>>>(H1, W2, H2,
                                                             N_NODES, F_OUT, F_HID);
    // out = 0 ; out += scatter(w * H2[src])
    {
        int n4 = N_NODES * F_OUT / 4;
        zero_kernel<<<(n4 + THREADS - 1) / THREADS, THREADS>>>((float4*)out, n4);
        spmm_kernel<F_OUT><<<spmm_blocks, THREADS>>>(esrc, edst, ew, H2, out);
    }
}

// round 6
// speedup vs baseline: 3.0478x; 1.2516x over previous
#include <cuda_runtime.h>
#include <cuda_bf16.h>

#define N_NODES 50000
#define N_EDGES 800000
#define F_IN    512
#define F_HID   256
#define F_OUT   128

// Scratch: H0 = X@W1, H1 = spmm(H0), H2 = relu(H1)@W2
__device__ float g_H0[(size_t)N_NODES * F_HID];
__device__ float g_H1[(size_t)N_NODES * F_HID];
__device__ float g_H2[(size_t)N_NODES * F_OUT];

// ---------------------------------------------------------------------------
// Zero kernel (float4)
// ---------------------------------------------------------------------------
__global__ void zero_kernel(float4* __restrict__ p, int n4) {
    int i = blockIdx.x * blockDim.x + threadIdx.x;
    if (i < n4) p[i] = make_float4(0.f, 0.f, 0.f, 0.f);
}

// ---------------------------------------------------------------------------
// helpers
// ---------------------------------------------------------------------------
// Split (f0,f1) into packed bf16x2 hi (leading 8 mantissa bits) and lo
// (residual). Low 16 bits of the register hold f0 (even k), matching the
// m16n8k16 fragment layout.
__device__ __forceinline__ void split_bf16x2(float f0, float f1,
                                             unsigned& hi, unsigned& lo) {
    asm("cvt.rn.bf16x2.f32 %0, %1, %2;" : "=r"(hi) : "f"(f1), "f"(f0));
    float fh0 = __uint_as_float(hi << 16);
    float fh1 = __uint_as_float(hi & 0xFFFF0000u);
    asm("cvt.rn.bf16x2.f32 %0, %1, %2;" : "=r"(lo)
        : "f"(f1 - fh1), "f"(f0 - fh0));
}

__device__ __forceinline__ void mma_bf16(float c[4], const unsigned a[4],
                                         const unsigned b[2]) {
    asm volatile(
        "mma.sync.aligned.m16n8k16.row.col.f32.bf16.bf16.f32 "
        "{%0,%1,%2,%3}, {%4,%5,%6,%7}, {%8,%9}, {%0,%1,%2,%3};"
        : "+f"(c[0]), "+f"(c[1]), "+f"(c[2]), "+f"(c[3])
        : "r"(a[0]), "r"(a[1]), "r"(a[2]), "r"(a[3]), "r"(b[0]), "r"(b[1]));
}

__device__ __forceinline__ unsigned smem_u32(const void* p) {
    return (unsigned)__cvta_generic_to_shared(p);
}

__device__ __forceinline__ void cp_async16(unsigned dst, const void* src, int src_bytes) {
    asm volatile("cp.async.ca.shared.global [%0], [%1], 16, %2;"
                 :: "r"(dst), "l"(src), "r"(src_bytes));
}
#define CP_COMMIT() asm volatile("cp.async.commit_group;")
#define CP_WAIT_1() asm volatile("cp.async.wait_group 1;")
#define CP_WAIT_0() asm volatile("cp.async.wait_group 0;")

// ---------------------------------------------------------------------------
// 3xBF16 tensor-core GEMM, cp.async double-buffered.
// C[M,N] = op(A)[M,K] @ B[K,N]. Block 128x128, BK=16, 8 warps (2x4),
// warp tile 64x32 (4 mtiles x 4 ntiles of m16n8k16).
// a = a_hi + a_lo (bf16 pair); D += a_lo*b_hi + a_hi*b_lo + a_hi*b_hi.
// Requires N % 128 == 0, K % 16 == 0. M bounds-checked.
// ---------------------------------------------------------------------------
template<bool RELU_A>
__global__ __launch_bounds__(256)
void gemm_tc_kernel(const float* __restrict__ A, const float* __restrict__ B,
                    float* __restrict__ C, int M, int N, int K) {
    constexpr int BM = 128, BN = 128, BK = 16;
    __shared__ __align__(16) float As[2][BM][BK + 4];   // [m][k], pitch 20
    __shared__ __align__(16) float Bs[2][BK][BN + 4];   // [k][n], pitch 132

    const int tid  = threadIdx.x;
    const int lane = tid & 31;
    const int warp = tid >> 5;
    const int g    = lane >> 2;     // groupID 0..7
    const int tig  = lane & 3;      // thread-in-group 0..3
    const int warp_m = warp & 1;    // 0..1 (64 rows each)
    const int warp_n = warp >> 1;   // 0..3 (32 cols each)

    const int row0 = blockIdx.y * BM;
    const int col0 = blockIdx.x * BN;

    float acc[4][4][4];
    #pragma unroll
    for (int i = 0; i < 4; i++)
        #pragma unroll
        for (int j = 0; j < 4; j++)
            #pragma unroll
            for (int l = 0; l < 4; l++) acc[i][j][l] = 0.f;

    auto load_tile = [&](int s, int k0) {
        // A: 128 rows x 16 cols = 512 float4; row = idx/4, kq = idx%4
        #pragma unroll
        for (int p = 0; p < 2; p++) {
            int idx = tid + p * 256;
            int m = idx >> 2, kq = idx & 3;
            int gr = row0 + m;
            const float* src = A + (size_t)(gr < M ? gr : 0) * K + k0 + kq * 4;
            cp_async16(smem_u32(&As[s][m][kq * 4]), src, gr < M ? 16 : 0);
        }
        // B: 16 rows x 128 cols = 512 float4; k = idx/32, cq = idx%32
        #pragma unroll
        for (int p = 0; p < 2; p++) {
            int idx = tid + p * 256;
            int kr = idx >> 5, cq = idx & 31;
            const float* src = B + (size_t)(k0 + kr) * N + col0 + cq * 4;
            cp_async16(smem_u32(&Bs[s][kr][cq * 4]), src, 16);
        }
    };

    auto compute = [&](int s) {
        // --- A fragments: 4 mtiles, each m16k16
        unsigned a_hi[4][4], a_lo[4][4];
        #pragma unroll
        for (int mt = 0; mt < 4; mt++) {
            int rb = warp_m * 64 + mt * 16 + g;
            float2 p0 = *(const float2*)(&As[s][rb    ][2 * tig]);
            float2 p1 = *(const float2*)(&As[s][rb + 8][2 * tig]);
            float2 p2 = *(const float2*)(&As[s][rb    ][2 * tig + 8]);
            float2 p3 = *(const float2*)(&As[s][rb + 8][2 * tig + 8]);
            if (RELU_A) {
                p0.x = fmaxf(p0.x, 0.f); p0.y = fmaxf(p0.y, 0.f);
                p1.x = fmaxf(p1.x, 0.f); p1.y = fmaxf(p1.y, 0.f);
                p2.x = fmaxf(p2.x, 0.f); p2.y = fmaxf(p2.y, 0.f);
                p3.x = fmaxf(p3.x, 0.f); p3.y = fmaxf(p3.y, 0.f);
            }
            split_bf16x2(p0.x, p0.y, a_hi[mt][0], a_lo[mt][0]);
            split_bf16x2(p1.x, p1.y, a_hi[mt][1], a_lo[mt][1]);
            split_bf16x2(p2.x, p2.y, a_hi[mt][2], a_lo[mt][2]);
            split_bf16x2(p3.x, p3.y, a_hi[mt][3], a_lo[mt][3]);
        }
        // --- B fragments: 4 ntiles, each k16n8
        unsigned b_hi[4][2], b_lo[4][2];
        #pragma unroll
        for (int nt = 0; nt < 4; nt++) {
            int cb = warp_n * 32 + nt * 8 + g;
            float f0 = Bs[s][2 * tig    ][cb];
            float f1 = Bs[s][2 * tig + 1][cb];
            float f2 = Bs[s][2 * tig + 8][cb];
            float f3 = Bs[s][2 * tig + 9][cb];
            split_bf16x2(f0, f1, b_hi[nt][0], b_lo[nt][0]);
            split_bf16x2(f2, f3, b_hi[nt][1], b_lo[nt][1]);
        }
        // --- 3xBF16 MMAs
        #pragma unroll
        for (int mt = 0; mt < 4; mt++)
            #pragma unroll
            for (int nt = 0; nt < 4; nt++) {
                mma_bf16(acc[mt][nt], a_lo[mt], b_hi[nt]);
                mma_bf16(acc[mt][nt], a_hi[mt], b_lo[nt]);
                mma_bf16(acc[mt][nt], a_hi[mt], b_hi[nt]);
            }
    };

    const int T = K / BK;
    load_tile(0, 0);
    CP_COMMIT();
    for (int t = 0; t < T; t++) {
        if (t + 1 < T) {
            load_tile((t + 1) & 1, (t + 1) * BK);
            CP_COMMIT();
            CP_WAIT_1();
        } else {
            CP_WAIT_0();
        }
        __syncthreads();
        compute(t & 1);
        __syncthreads();
    }

    // ---- store C
    #pragma unroll
    for (int mt = 0; mt < 4; mt++) {
        int r_lo = row0 + warp_m * 64 + mt * 16 + g;
        int r_hi = r_lo + 8;
        #pragma unroll
        for (int nt = 0; nt < 4; nt++) {
            int c = col0 + warp_n * 32 + nt * 8 + 2 * tig;
            if (r_lo < M)
                *(float2*)(C + (size_t)r_lo * N + c) =
                    make_float2(acc[mt][nt][0], acc[mt][nt][1]);
            if (r_hi < M)
                *(float2*)(C + (size_t)r_hi * N + c) =
                    make_float2(acc[mt][nt][2], acc[mt][nt][3]);
        }
    }
}

// ---------------------------------------------------------------------------
// Warp-per-edge SpMM: y[dst[e]] += w[e] * x[src[e]]
// ---------------------------------------------------------------------------
template<int F>
__global__ __launch_bounds__(256)
void spmm_kernel(const int* __restrict__ src, const int* __restrict__ dst,
                 const float* __restrict__ w, const float* __restrict__ x,
                 float* __restrict__ y) {
    constexpr int F4 = F / 4;
    int e = blockIdx.x * 8 + (threadIdx.x >> 5);
    if (e >= N_EDGES) return;
    int lane = threadIdx.x & 31;

    float wv = __ldg(&w[e]);
    int s = __ldg(&src[e]);
    int d = __ldg(&dst[e]);

    const float4* xr = (const float4*)(x + (size_t)s * F);
    float* yr = y + (size_t)d * F;

    #pragma unroll
    for (int c = lane; c < F4; c += 32) {
        float4 v = __ldg(&xr[c]);
        float* yp = yr + c * 4;
        asm volatile("red.global.add.v4.f32 [%0], {%1, %2, %3, %4};"
                     :: "l"(yp), "f"(wv * v.x), "f"(wv * v.y),
                        "f"(wv * v.z), "f"(wv * v.w)
                     : "memory");
    }
}

// ---------------------------------------------------------------------------
// Launch
// ---------------------------------------------------------------------------
extern "C" void kernel_launch(void* const* d_in, const int* in_sizes, int n_in,
                              void* d_out, int out_size) {
    const float* X    = (const float*)d_in[0];   // [N_NODES, F_IN]
    const int*   esrc = (const int*)  d_in[1];   // [N_EDGES]
    const int*   edst = (const int*)  d_in[2];   // [N_EDGES]
    const float* ew   = (const float*)d_in[3];   // [N_EDGES]
    const float* W1   = (const float*)d_in[4];   // [F_IN, F_HID]
    const float* W2   = (const float*)d_in[5];   // [F_HID, F_OUT]
    float* out = (float*)d_out;                  // [N_NODES, F_OUT]

    float *H0, *H1, *H2;
    cudaGetSymbolAddress((void**)&H0, g_H0);
    cudaGetSymbolAddress((void**)&H1, g_H1);
    cudaGetSymbolAddress((void**)&H2, g_H2);

    const int THREADS = 256;
    const int MB = (N_NODES + 127) / 128;
    const int spmm_blocks = (N_EDGES + 7) / 8;

    // H0 = X @ W1
    gemm_tc_kernel<false><<<dim3(F_HID / 128, MB), THREADS>>>(X, W1, H0,
                                                              N_NODES, F_HID, F_IN);
    // H1 = 0 ; H1 += scatter(w * H0[src])
    {
        int n4 = N_NODES * F_HID / 4;
        zero_kernel<<<(n4 + THREADS - 1) / THREADS, THREADS>>>((float4*)H1, n4);
        spmm_kernel<F_HID><<<spmm_blocks, THREADS>>>(esrc, edst, ew, H0, H1);
    }
    // H2 = relu(H1) @ W2
    gemm_tc_kernel<true><<<dim3(F_OUT / 128, MB), THREADS>>>(H1, W2, H2,
                                                             N_NODES, F_OUT, F_HID);
    // out = 0 ; out += scatter(w * H2[src])
    {
        int n4 = N_NODES * F_OUT / 4;
        zero_kernel<<<(n4 + THREADS - 1) / THREADS, THREADS>>>((float4*)out, n4);
        spmm_kernel<F_OUT><<<spmm_blocks, THREADS>>>(esrc, edst, ew, H2, out);
    }
}

// round 7
// speedup vs baseline: 3.2584x; 1.0691x over previous
#include <cuda_runtime.h>
#include <cuda_bf16.h>

#define N_NODES 50000
#define N_EDGES 800000
#define F_IN    512
#define F_HID   256
#define F_OUT   128

// Scratch: H0 = X@W1, H1 = spmm(H0), H2 = relu(H1)@W2
__device__ float g_H0[(size_t)N_NODES * F_HID];
__device__ float g_H1[(size_t)N_NODES * F_HID];
__device__ float g_H2[(size_t)N_NODES * F_OUT];

// ---------------------------------------------------------------------------
// Zero kernel (float4)
// ---------------------------------------------------------------------------
__global__ void zero_kernel(float4* __restrict__ p, int n4) {
    int i = blockIdx.x * blockDim.x + threadIdx.x;
    if (i < n4) p[i] = make_float4(0.f, 0.f, 0.f, 0.f);
}

// ---------------------------------------------------------------------------
// helpers
// ---------------------------------------------------------------------------
// Split (f0,f1) into packed bf16x2 hi and lo residual. f0 in low 16 bits
// (even k), f1 in high (odd k) — matches m16n8k16 fragment layout.
__device__ __forceinline__ void split_bf16x2(float f0, float f1,
                                             unsigned& hi, unsigned& lo) {
    asm("cvt.rn.bf16x2.f32 %0, %1, %2;" : "=r"(hi) : "f"(f1), "f"(f0));
    float fh0 = __uint_as_float(hi << 16);
    float fh1 = __uint_as_float(hi & 0xFFFF0000u);
    asm("cvt.rn.bf16x2.f32 %0, %1, %2;" : "=r"(lo)
        : "f"(f1 - fh1), "f"(f0 - fh0));
}

__device__ __forceinline__ void mma_bf16(float c[4], const unsigned a[4],
                                         const unsigned b[2]) {
    asm volatile(
        "mma.sync.aligned.m16n8k16.row.col.f32.bf16.bf16.f32 "
        "{%0,%1,%2,%3}, {%4,%5,%6,%7}, {%8,%9}, {%0,%1,%2,%3};"
        : "+f"(c[0]), "+f"(c[1]), "+f"(c[2]), "+f"(c[3])
        : "r"(a[0]), "r"(a[1]), "r"(a[2]), "r"(a[3]), "r"(b[0]), "r"(b[1]));
}

// ---------------------------------------------------------------------------
// 3xBF16 tensor-core GEMM, split-at-store, register-staged double buffer.
// C[M,N] = op(A)[M,K] @ B[K,N]. Block 128x128, BK=16, 8 warps (2x4),
// warp tile 64x32 (4 mtiles x 4 ntiles of m16n8k16).
// Smem holds pre-split bf16 k-pair-packed u32 in fragment register format:
//   As[m][kp]  (kp = k/2, pitch 12)   a-reg = 1 LDS.32
//   Bs[kp][n]  (pitch 136)            b-reg = 1 LDS.32
// Requires N % 128 == 0, K % 16 == 0. M bounds-checked.
// ---------------------------------------------------------------------------
template<bool RELU_A>
__global__ __launch_bounds__(256, 2)
void gemm_tc_kernel(const float* __restrict__ A, const float* __restrict__ B,
                    float* __restrict__ C, int M, int N, int K) {
    constexpr int BM = 128, BK = 16;
    constexpr int AP = 12;    // A pitch in u32 (8 kpairs + pad) — bank-clean
    constexpr int BP = 136;   // B pitch in u32 (128 cols + pad) — bank-clean
    __shared__ __align__(16) unsigned As_hi[2][BM * AP];
    __shared__ __align__(16) unsigned As_lo[2][BM * AP];
    __shared__ __align__(16) unsigned Bs_hi[2][8 * BP];
    __shared__ __align__(16) unsigned Bs_lo[2][8 * BP];

    const int tid  = threadIdx.x;
    const int lane = tid & 31;
    const int warp = tid >> 5;
    const int g    = lane >> 2;     // 0..7
    const int tig  = lane & 3;      // 0..3
    const int warp_m = warp & 1;    // 0..1 (64 rows)
    const int warp_n = warp >> 1;   // 0..3 (32 cols)

    const int row0 = blockIdx.y * BM;
    const int col0 = blockIdx.x * 128;

    // loader maps
    const int a_m0 = tid >> 2;          // 0..63  (+64 for p=1)
    const int a_kq = tid & 3;           // float4 at k = a_kq*4
    const int b_kp = tid >> 5;          // 0..7
    const int b_cq = (tid & 31) * 4;    // col group

    float acc[4][4][4];
    #pragma unroll
    for (int i = 0; i < 4; i++)
        #pragma unroll
        for (int j = 0; j < 4; j++)
            #pragma unroll
            for (int l = 0; l < 4; l++) acc[i][j][l] = 0.f;

    float4 a_reg[2], b_reg[2];

    auto ldg_tile = [&](int k0) {
        #pragma unroll
        for (int p = 0; p < 2; p++) {
            int m = a_m0 + p * 64;
            int gr = row0 + m;
            if (gr < M)
                a_reg[p] = *(const float4*)(A + (size_t)gr * K + k0 + a_kq * 4);
            else
                a_reg[p] = make_float4(0.f, 0.f, 0.f, 0.f);
        }
        b_reg[0] = *(const float4*)(B + (size_t)(k0 + 2 * b_kp)     * N + col0 + b_cq);
        b_reg[1] = *(const float4*)(B + (size_t)(k0 + 2 * b_kp + 1) * N + col0 + b_cq);
    };

    auto sts_tile = [&](int s) {
        #pragma unroll
        for (int p = 0; p < 2; p++) {
            int m = a_m0 + p * 64;
            float4 v = a_reg[p];
            if (RELU_A) {
                v.x = fmaxf(v.x, 0.f); v.y = fmaxf(v.y, 0.f);
                v.z = fmaxf(v.z, 0.f); v.w = fmaxf(v.w, 0.f);
            }
            unsigned h0, l0, h1, l1;
            split_bf16x2(v.x, v.y, h0, l0);   // kpair a_kq*2
            split_bf16x2(v.z, v.w, h1, l1);   // kpair a_kq*2+1
            int off = m * AP + a_kq * 2;
            *(uint2*)&As_hi[s][off] = make_uint2(h0, h1);
            *(uint2*)&As_lo[s][off] = make_uint2(l0, l1);
        }
        {
            // b_reg[0] = row 2kp (even k), b_reg[1] = row 2kp+1 (odd k)
            unsigned h[4], l[4];
            split_bf16x2(b_reg[0].x, b_reg[1].x, h[0], l[0]);
            split_bf16x2(b_reg[0].y, b_reg[1].y, h[1], l[1]);
            split_bf16x2(b_reg[0].z, b_reg[1].z, h[2], l[2]);
            split_bf16x2(b_reg[0].w, b_reg[1].w, h[3], l[3]);
            int off = b_kp * BP + b_cq;
            *(uint4*)&Bs_hi[s][off] = make_uint4(h[0], h[1], h[2], h[3]);
            *(uint4*)&Bs_lo[s][off] = make_uint4(l[0], l[1], l[2], l[3]);
        }
    };

    auto compute = [&](int s) {
        unsigned b_hi[4][2], b_lo[4][2];
        #pragma unroll
        for (int nt = 0; nt < 4; nt++) {
            int cb = warp_n * 32 + nt * 8 + g;
            b_hi[nt][0] = Bs_hi[s][tig * BP + cb];
            b_hi[nt][1] = Bs_hi[s][(tig + 4) * BP + cb];
            b_lo[nt][0] = Bs_lo[s][tig * BP + cb];
            b_lo[nt][1] = Bs_lo[s][(tig + 4) * BP + cb];
        }
        #pragma unroll
        for (int mt = 0; mt < 4; mt++) {
            int rb = warp_m * 64 + mt * 16 + g;
            unsigned a_hi[4], a_lo[4];
            a_hi[0] = As_hi[s][rb * AP + tig];
            a_hi[1] = As_hi[s][(rb + 8) * AP + tig];
            a_hi[2] = As_hi[s][rb * AP + tig + 4];
            a_hi[3] = As_hi[s][(rb + 8) * AP + tig + 4];
            a_lo[0] = As_lo[s][rb * AP + tig];
            a_lo[1] = As_lo[s][(rb + 8) * AP + tig];
            a_lo[2] = As_lo[s][rb * AP + tig + 4];
            a_lo[3] = As_lo[s][(rb + 8) * AP + tig + 4];
            #pragma unroll
            for (int nt = 0; nt < 4; nt++) {
                mma_bf16(acc[mt][nt], a_lo, b_hi[nt]);
                mma_bf16(acc[mt][nt], a_hi, b_lo[nt]);
                mma_bf16(acc[mt][nt], a_hi, b_hi[nt]);
            }
        }
    };

    const int T = K / BK;
    ldg_tile(0);
    for (int t = 0; t < T; t++) {
        sts_tile(t & 1);
        __syncthreads();
        if (t + 1 < T) ldg_tile((t + 1) * BK);   // overlaps compute below
        compute(t & 1);
        // one sync per iter: buffer (t+1)&1 was last read in compute(t-1),
        // separated from the next sts by the sync above.
    }

    // ---- store C
    #pragma unroll
    for (int mt = 0; mt < 4; mt++) {
        int r_lo = row0 + warp_m * 64 + mt * 16 + g;
        int r_hi = r_lo + 8;
        #pragma unroll
        for (int nt = 0; nt < 4; nt++) {
            int c = col0 + warp_n * 32 + nt * 8 + 2 * tig;
            if (r_lo < M)
                *(float2*)(C + (size_t)r_lo * N + c) =
                    make_float2(acc[mt][nt][0], acc[mt][nt][1]);
            if (r_hi < M)
                *(float2*)(C + (size_t)r_hi * N + c) =
                    make_float2(acc[mt][nt][2], acc[mt][nt][3]);
        }
    }
}

// ---------------------------------------------------------------------------
// Warp-per-edge SpMM: y[dst[e]] += w[e] * x[src[e]]
// ---------------------------------------------------------------------------
template<int F>
__global__ __launch_bounds__(256)
void spmm_kernel(const int* __restrict__ src, const int* __restrict__ dst,
                 const float* __restrict__ w, const float* __restrict__ x,
                 float* __restrict__ y) {
    constexpr int F4 = F / 4;
    int e = blockIdx.x * 8 + (threadIdx.x >> 5);
    if (e >= N_EDGES) return;
    int lane = threadIdx.x & 31;

    float wv = __ldg(&w[e]);
    int s = __ldg(&src[e]);
    int d = __ldg(&dst[e]);

    const float4* xr = (const float4*)(x + (size_t)s * F);
    float* yr = y + (size_t)d * F;

    #pragma unroll
    for (int c = lane; c < F4; c += 32) {
        float4 v = __ldg(&xr[c]);
        float* yp = yr + c * 4;
        asm volatile("red.global.add.v4.f32 [%0], {%1, %2, %3, %4};"
                     :: "l"(yp), "f"(wv * v.x), "f"(wv * v.y),
                        "f"(wv * v.z), "f"(wv * v.w)
                     : "memory");
    }
}

// ---------------------------------------------------------------------------
// Launch
// ---------------------------------------------------------------------------
extern "C" void kernel_launch(void* const* d_in, const int* in_sizes, int n_in,
                              void* d_out, int out_size) {
    const float* X    = (const float*)d_in[0];   // [N_NODES, F_IN]
    const int*   esrc = (const int*)  d_in[1];   // [N_EDGES]
    const int*   edst = (const int*)  d_in[2];   // [N_EDGES]
    const float* ew   = (const float*)d_in[3];   // [N_EDGES]
    const float* W1   = (const float*)d_in[4];   // [F_IN, F_HID]
    const float* W2   = (const float*)d_in[5];   // [F_HID, F_OUT]
    float* out = (float*)d_out;                  // [N_NODES, F_OUT]

    float *H0, *H1, *H2;
    cudaGetSymbolAddress((void**)&H0, g_H0);
    cudaGetSymbolAddress((void**)&H1, g_H1);
    cudaGetSymbolAddress((void**)&H2, g_H2);

    const int THREADS = 256;
    const int MB = (N_NODES + 127) / 128;
    const int spmm_blocks = (N_EDGES + 7) / 8;

    // H0 = X @ W1
    gemm_tc_kernel<false><<<dim3(F_HID / 128, MB), THREADS>>>(X, W1, H0,
                                                              N_NODES, F_HID, F_IN);
    // H1 = 0 ; H1 += scatter(w * H0[src])
    {
        int n4 = N_NODES * F_HID / 4;
        zero_kernel<<<(n4 + THREADS - 1) / THREADS, THREADS>>>((float4*)H1, n4);
        spmm_kernel<F_HID><<<spmm_blocks, THREADS>>>(esrc, edst, ew, H0, H1);
    }
    // H2 = relu(H1) @ W2
    gemm_tc_kernel<true><<<dim3(F_OUT / 128, MB), THREADS>>>(H1, W2, H2,
                                                             N_NODES, F_OUT, F_HID);
    // out = 0 ; out += scatter(w * H2[src])
    {
        int n4 = N_NODES * F_OUT / 4;
        zero_kernel<<<(n4 + THREADS - 1) / THREADS, THREADS>>>((float4*)out, n4);
        spmm_kernel<F_OUT><<<spmm_blocks, THREADS>>>(esrc, edst, ew, H2, out);
    }
}

// round 9
// speedup vs baseline: 4.7861x; 1.4689x over previous
#include <cuda_runtime.h>
#include <cuda_bf16.h>

#define N_NODES 50000
#define N_EDGES 800000
#define F_IN    512
#define F_HID   256
#define F_OUT   128

#define SCAN_BLOCKS 64           // 64 * 1024 >= N_NODES

// Scratch
__device__ float g_H0[(size_t)N_NODES * F_HID];
__device__ float g_H1[(size_t)N_NODES * F_HID];
__device__ float g_H2[(size_t)N_NODES * F_OUT];
__device__ int   g_deg[N_NODES];
__device__ int   g_part[N_NODES];
__device__ int   g_bsum[SCAN_BLOCKS];
__device__ int   g_offsets[N_NODES + 1];
__device__ int   g_cursor[N_NODES];
__device__ int   g_ssrc[N_EDGES];
__device__ float g_sw[N_EDGES];

// ---------------------------------------------------------------------------
// CSR build kernels
// ---------------------------------------------------------------------------
__global__ void zero_deg_kernel() {
    int i = blockIdx.x * blockDim.x + threadIdx.x;
    if (i < N_NODES) g_deg[i] = 0;
}

__global__ void hist_kernel(const int* __restrict__ dst) {
    int e = blockIdx.x * blockDim.x + threadIdx.x;
    if (e < N_EDGES) atomicAdd(&g_deg[dst[e]], 1);
}

__global__ __launch_bounds__(1024)
void scan_blocks_kernel() {
    __shared__ int sm[1024];
    int tid = threadIdx.x;
    int i = blockIdx.x * 1024 + tid;
    int v = (i < N_NODES) ? g_deg[i] : 0;
    sm[tid] = v;
    __syncthreads();
    #pragma unroll
    for (int d = 1; d < 1024; d <<= 1) {
        int t = (tid >= d) ? sm[tid - d] : 0;
        __syncthreads();
        sm[tid] += t;
        __syncthreads();
    }
    if (i < N_NODES) g_part[i] = sm[tid] - v;       // exclusive within block
    if (tid == 1023) g_bsum[blockIdx.x] = sm[1023]; // block total
}

__global__ void scan_sums_kernel() {   // 1 block, SCAN_BLOCKS threads
    __shared__ int sm[SCAN_BLOCKS];
    int tid = threadIdx.x;
    int v = g_bsum[tid];
    sm[tid] = v;
    __syncthreads();
    #pragma unroll
    for (int d = 1; d < SCAN_BLOCKS; d <<= 1) {
        int t = (tid >= d) ? sm[tid - d] : 0;
        __syncthreads();
        sm[tid] += t;
        __syncthreads();
    }
    g_bsum[tid] = sm[tid] - v;         // exclusive
}

__global__ void add_off_kernel() {
    int i = blockIdx.x * blockDim.x + threadIdx.x;
    if (i < N_NODES) {
        int off = g_part[i] + g_bsum[i >> 10];
        g_offsets[i] = off;
        g_cursor[i]  = off;
    }
    if (i == 0) g_offsets[N_NODES] = N_EDGES;
}

__global__ void fill_kernel(const int* __restrict__ src,
                            const int* __restrict__ dst,
                            const float* __restrict__ w) {
    int e = blockIdx.x * blockDim.x + threadIdx.x;
    if (e >= N_EDGES) return;
    int d = dst[e];
    int pos = atomicAdd(&g_cursor[d], 1);
    g_ssrc[pos] = src[e];
    g_sw[pos]   = w[e];
}

// ---------------------------------------------------------------------------
// CSR SpMM: warp per node, register accumulation, one coalesced store.
// y[i] = sum_{j in [off[i],off[i+1])} sw[j] * x[ssrc[j]]
// ---------------------------------------------------------------------------
template<int F>
__global__ __launch_bounds__(256)
void spmm_csr_kernel(const float* __restrict__ x, float* __restrict__ y) {
    int node = (blockIdx.x * 256 + threadIdx.x) >> 5;
    if (node >= N_NODES) return;
    int lane = threadIdx.x & 31;

    int beg = g_offsets[node];
    int end = g_offsets[node + 1];

    float4 acc0 = make_float4(0.f, 0.f, 0.f, 0.f);
    float4 acc1 = make_float4(0.f, 0.f, 0.f, 0.f);   // used only if F==256

    for (int j = beg; j < end; j++) {
        int s    = __ldg(&g_ssrc[j]);
        float wv = __ldg(&g_sw[j]);
        const float4* xr = (const float4*)(x + (size_t)s * F);
        float4 v0 = __ldg(&xr[lane]);
        acc0.x = fmaf(wv, v0.x, acc0.x);
        acc0.y = fmaf(wv, v0.y, acc0.y);
        acc0.z = fmaf(wv, v0.z, acc0.z);
        acc0.w = fmaf(wv, v0.w, acc0.w);
        if (F == 256) {
            float4 v1 = __ldg(&xr[lane + 32]);
            acc1.x = fmaf(wv, v1.x, acc1.x);
            acc1.y = fmaf(wv, v1.y, acc1.y);
            acc1.z = fmaf(wv, v1.z, acc1.z);
            acc1.w = fmaf(wv, v1.w, acc1.w);
        }
    }

    float4* yr = (float4*)(y + (size_t)node * F);
    yr[lane] = acc0;
    if (F == 256) yr[lane + 32] = acc1;
}

// ---------------------------------------------------------------------------
// GEMM helpers (3xBF16 split, as Round 7)
// ---------------------------------------------------------------------------
__device__ __forceinline__ void split_bf16x2(float f0, float f1,
                                             unsigned& hi, unsigned& lo) {
    asm("cvt.rn.bf16x2.f32 %0, %1, %2;" : "=r"(hi) : "f"(f1), "f"(f0));
    float fh0 = __uint_as_float(hi << 16);
    float fh1 = __uint_as_float(hi & 0xFFFF0000u);
    asm("cvt.rn.bf16x2.f32 %0, %1, %2;" : "=r"(lo)
        : "f"(f1 - fh1), "f"(f0 - fh0));
}

__device__ __forceinline__ void mma_bf16(float c[4], const unsigned a[4],
                                         const unsigned b[2]) {
    asm volatile(
        "mma.sync.aligned.m16n8k16.row.col.f32.bf16.bf16.f32 "
        "{%0,%1,%2,%3}, {%4,%5,%6,%7}, {%8,%9}, {%0,%1,%2,%3};"
        : "+f"(c[0]), "+f"(c[1]), "+f"(c[2]), "+f"(c[3])
        : "r"(a[0]), "r"(a[1]), "r"(a[2]), "r"(a[3]), "r"(b[0]), "r"(b[1]));
}

template<bool RELU_A>
__global__ __launch_bounds__(256, 2)
void gemm_tc_kernel(const float* __restrict__ A, const float* __restrict__ B,
                    float* __restrict__ C, int M, int N, int K) {
    constexpr int BM = 128, BK = 16;
    constexpr int AP = 12;
    constexpr int BP = 136;
    __shared__ __align__(16) unsigned As_hi[2][BM * AP];
    __shared__ __align__(16) unsigned As_lo[2][BM * AP];
    __shared__ __align__(16) unsigned Bs_hi[2][8 * BP];
    __shared__ __align__(16) unsigned Bs_lo[2][8 * BP];

    const int tid  = threadIdx.x;
    const int lane = tid & 31;
    const int warp = tid >> 5;
    const int g    = lane >> 2;
    const int tig  = lane & 3;
    const int warp_m = warp & 1;
    const int warp_n = warp >> 1;

    const int row0 = blockIdx.y * BM;
    const int col0 = blockIdx.x * 128;

    const int a_m0 = tid >> 2;
    const int a_kq = tid & 3;
    const int b_kp = tid >> 5;
    const int b_cq = (tid & 31) * 4;

    float acc[4][4][4];
    #pragma unroll
    for (int i = 0; i < 4; i++)
        #pragma unroll
        for (int j = 0; j < 4; j++)
            #pragma unroll
            for (int l = 0; l < 4; l++) acc[i][j][l] = 0.f;

    float4 a_reg[2], b_reg[2];

    auto ldg_tile = [&](int k0) {
        #pragma unroll
        for (int p = 0; p < 2; p++) {
            int m = a_m0 + p * 64;
            int gr = row0 + m;
            if (gr < M)
                a_reg[p] = *(const float4*)(A + (size_t)gr * K + k0 + a_kq * 4);
            else
                a_reg[p] = make_float4(0.f, 0.f, 0.f, 0.f);
        }
        b_reg[0] = *(const float4*)(B + (size_t)(k0 + 2 * b_kp)     * N + col0 + b_cq);
        b_reg[1] = *(const float4*)(B + (size_t)(k0 + 2 * b_kp + 1) * N + col0 + b_cq);
    };

    auto sts_tile = [&](int s) {
        #pragma unroll
        for (int p = 0; p < 2; p++) {
            int m = a_m0 + p * 64;
            float4 v = a_reg[p];
            if (RELU_A) {
                v.x = fmaxf(v.x, 0.f); v.y = fmaxf(v.y, 0.f);
                v.z = fmaxf(v.z, 0.f); v.w = fmaxf(v.w, 0.f);
            }
            unsigned h0, l0, h1, l1;
            split_bf16x2(v.x, v.y, h0, l0);
            split_bf16x2(v.z, v.w, h1, l1);
            int off = m * AP + a_kq * 2;
            *(uint2*)&As_hi[s][off] = make_uint2(h0, h1);
            *(uint2*)&As_lo[s][off] = make_uint2(l0, l1);
        }
        {
            unsigned h[4], l[4];
            split_bf16x2(b_reg[0].x, b_reg[1].x, h[0], l[0]);
            split_bf16x2(b_reg[0].y, b_reg[1].y, h[1], l[1]);
            split_bf16x2(b_reg[0].z, b_reg[1].z, h[2], l[2]);
            split_bf16x2(b_reg[0].w, b_reg[1].w, h[3], l[3]);
            int off = b_kp * BP + b_cq;
            *(uint4*)&Bs_hi[s][off] = make_uint4(h[0], h[1], h[2], h[3]);
            *(uint4*)&Bs_lo[s][off] = make_uint4(l[0], l[1], l[2], l[3]);
        }
    };

    auto compute = [&](int s) {
        unsigned b_hi[4][2], b_lo[4][2];
        #pragma unroll
        for (int nt = 0; nt < 4; nt++) {
            int cb = warp_n * 32 + nt * 8 + g;
            b_hi[nt][0] = Bs_hi[s][tig * BP + cb];
            b_hi[nt][1] = Bs_hi[s][(tig + 4) * BP + cb];
            b_lo[nt][0] = Bs_lo[s][tig * BP + cb];
            b_lo[nt][1] = Bs_lo[s][(tig + 4) * BP + cb];
        }
        #pragma unroll
        for (int mt = 0; mt < 4; mt++) {
            int rb = warp_m * 64 + mt * 16 + g;
            unsigned a_hi[4], a_lo[4];
            a_hi[0] = As_hi[s][rb * AP + tig];
            a_hi[1] = As_hi[s][(rb + 8) * AP + tig];
            a_hi[2] = As_hi[s][rb * AP + tig + 4];
            a_hi[3] = As_hi[s][(rb + 8) * AP + tig + 4];
            a_lo[0] = As_lo[s][rb * AP + tig];
            a_lo[1] = As_lo[s][(rb + 8) * AP + tig];
            a_lo[2] = As_lo[s][rb * AP + tig + 4];
            a_lo[3] = As_lo[s][(rb + 8) * AP + tig + 4];
            #pragma unroll
            for (int nt = 0; nt < 4; nt++) {
                mma_bf16(acc[mt][nt], a_lo, b_hi[nt]);
                mma_bf16(acc[mt][nt], a_hi, b_lo[nt]);
                mma_bf16(acc[mt][nt], a_hi, b_hi[nt]);
            }
        }
    };

    const int T = K / BK;
    ldg_tile(0);
    for (int t = 0; t < T; t++) {
        sts_tile(t & 1);
        __syncthreads();
        if (t + 1 < T) ldg_tile((t + 1) * BK);
        compute(t & 1);
    }

    #pragma unroll
    for (int mt = 0; mt < 4; mt++) {
        int r_lo = row0 + warp_m * 64 + mt * 16 + g;
        int r_hi = r_lo + 8;
        #pragma unroll
        for (int nt = 0; nt < 4; nt++) {
            int c = col0 + warp_n * 32 + nt * 8 + 2 * tig;
            if (r_lo < M)
                *(float2*)(C + (size_t)r_lo * N + c) =
                    make_float2(acc[mt][nt][0], acc[mt][nt][1]);
            if (r_hi < M)
                *(float2*)(C + (size_t)r_hi * N + c) =
                    make_float2(acc[mt][nt][2], acc[mt][nt][3]);
        }
    }
}

// ---------------------------------------------------------------------------
// Launch
// ---------------------------------------------------------------------------
extern "C" void kernel_launch(void* const* d_in, const int* in_sizes, int n_in,
                              void* d_out, int out_size) {
    const float* X    = (const float*)d_in[0];
    const int*   esrc = (const int*)  d_in[1];
    const int*   edst = (const int*)  d_in[2];
    const float* ew   = (const float*)d_in[3];
    const float* W1   = (const float*)d_in[4];
    const float* W2   = (const float*)d_in[5];
    float* out = (float*)d_out;

    float *H0, *H1, *H2;
    cudaGetSymbolAddress((void**)&H0, g_H0);
    cudaGetSymbolAddress((void**)&H1, g_H1);
    cudaGetSymbolAddress((void**)&H2, g_H2);

    const int T = 256;
    const int MB = (N_NODES + 127) / 128;
    const int node_blocks = (N_NODES + T - 1) / T;
    const int edge_blocks = (N_EDGES + T - 1) / T;
    const int spmm_blocks = (N_NODES * 32 + T - 1) / T;   // warp per node

    // ---- CSR build (graph shared by both layers)
    zero_deg_kernel<<<node_blocks, T>>>();
    hist_kernel<<<edge_blocks, T>>>(edst);
    scan_blocks_kernel<<<SCAN_BLOCKS, 1024>>>();
    scan_sums_kernel<<<1, SCAN_BLOCKS>>>();
    add_off_kernel<<<node_blocks, T>>>();
    fill_kernel<<<edge_blocks, T>>>(esrc, edst, ew);

    // ---- layer 1
    gemm_tc_kernel<false><<<dim3(F_HID / 128, MB), T>>>(X, W1, H0,
                                                        N_NODES, F_HID, F_IN);
    spmm_csr_kernel<F_HID><<<spmm_blocks, T>>>(H0, H1);

    // ---- layer 2
    gemm_tc_kernel<true><<<dim3(F_OUT / 128, MB), T>>>(H1, W2, H2,
                                                       N_NODES, F_OUT, F_HID);
    spmm_csr_kernel<F_OUT><<<spmm_blocks, T>>>(H2, out);
}